// round 14
// baseline (speedup 1.0000x reference)
#include <cuda_runtime.h>
#include <cuda_fp16.h>
#include <math_constants.h>
#include <mma.h>
#include <cstdint>

using namespace nvcuda;

#define BB 2
#define TT 2048
#define NE 2048
#define NH 16
#define NKV 4
#define HD 128
#define GRP (NH / NKV)
#define MROWS (BB * TT)
#define KVE (NKV * HD)

// fp16 scratch
__device__ __half g_x[MROWS * NE];
__device__ __half g_wq[NE * NE];
__device__ __half g_wk[KVE * NE];
__device__ __half g_wv[KVE * NE];
__device__ __half g_wo[NE * NE];
__device__ __half g_q[MROWS * NE];     // (B,T,H,D)
__device__ __half g_k[MROWS * KVE];    // (B,T,Hkv,D)
__device__ __half g_vt[MROWS * KVE];   // (B,Hkv,D,T)
__device__ __half g_y[MROWS * NE];

__device__ __forceinline__ uint32_t pack_h(float x, float y) {
    __half2 r = __floats2half2_rn(x, y);
    return *(uint32_t*)&r;
}
__device__ __forceinline__ float fast_exp2(float x) {
    float y; asm("ex2.approx.f32 %0, %1;" : "=f"(y) : "f"(x)); return y;
}
__device__ __forceinline__ void mma16816(float* c, const uint32_t* a, uint32_t b0, uint32_t b1) {
    asm volatile("mma.sync.aligned.m16n8k16.row.col.f32.f16.f16.f32 "
                 "{%0,%1,%2,%3}, {%4,%5,%6,%7}, {%8,%9}, {%0,%1,%2,%3};\n"
                 : "+f"(c[0]), "+f"(c[1]), "+f"(c[2]), "+f"(c[3])
                 : "r"(a[0]), "r"(a[1]), "r"(a[2]), "r"(a[3]), "r"(b0), "r"(b1));
}
__device__ __forceinline__ void cp16(__half* s, const __half* g) {
    uint32_t sa = (uint32_t)__cvta_generic_to_shared(s);
    asm volatile("cp.async.cg.shared.global [%0], [%1], 16;" :: "r"(sa), "l"(g));
}

// ---------------------------------------------------------------------------
// Fused prep: convert x, wq, wk, wv, wo -> single fp16
// ---------------------------------------------------------------------------
#define NX4  (MROWS * NE / 4)
#define NW4  (NE * NE / 4)
#define NWK4 (KVE * NE / 4)
#define PREP_TOTAL (NX4 + NW4 + 2 * NWK4 + NW4)

__global__ __launch_bounds__(256) void prep_all(
    const float* __restrict__ x,  const float* __restrict__ wq,
    const float* __restrict__ wk, const float* __restrict__ wv,
    const float* __restrict__ wo,
    __half* __restrict__ xp, __half* __restrict__ wqp,
    __half* __restrict__ wkp, __half* __restrict__ wvp,
    __half* __restrict__ wop)
{
    int i = blockIdx.x * blockDim.x + threadIdx.x;
    if (i >= PREP_TOTAL) return;
    const float* src; __half* dst; int j;
    if (i < NX4)                        { src = x;  dst = xp;  j = i; }
    else if (i < NX4 + NW4)             { src = wq; dst = wqp; j = i - NX4; }
    else if (i < NX4 + NW4 + NWK4)      { src = wk; dst = wkp; j = i - NX4 - NW4; }
    else if (i < NX4 + NW4 + 2*NWK4)    { src = wv; dst = wvp; j = i - NX4 - NW4 - NWK4; }
    else                                { src = wo; dst = wop; j = i - NX4 - NW4 - 2*NWK4; }
    float4 v = ((const float4*)src)[j];
    union { __half b[4]; uint2 u; } H;
    H.b[0] = __float2half_rn(v.x); H.b[1] = __float2half_rn(v.y);
    H.b[2] = __float2half_rn(v.z); H.b[3] = __float2half_rn(v.w);
    ((uint2*)dst)[j] = H.u;
}

// ---------------------------------------------------------------------------
// GEMM core: 3-stage cp.async, K-step 64, fp16 1-term.
// Block tile 128x128, 256 threads, 8 warps as 4x2, warp tile 32x64.
// 110,592 B smem/CTA -> 2 CTAs/SM.
// ---------------------------------------------------------------------------
#define TBM 128
#define TBN 128
#define TBK 64
#define TLD 72
#define TILE_ELEMS (TBM * TLD)     // 9216 halves
#define NSTAGE 3
#define SEPI 132
#define GEMM_SMEM (NSTAGE * 2 * TILE_ELEMS * 2)   // 110,592 B

__device__ __forceinline__ void g_load_stage(
    __half* gsm, int st, int kb, int t,
    const __half* A, const __half* B,
    int row0, int col0, int K)
{
    __half* tA = gsm + (st * 2 + 0) * TILE_ELEMS;
    __half* tB = gsm + (st * 2 + 1) * TILE_ELEMS;
#pragma unroll
    for (int i = 0; i < 4; i++) {
        int p = t + i * 256;
        int r = p >> 3, ch = p & 7;
        size_t ga = (size_t)(row0 + r) * K + kb * TBK + ch * 8;
        size_t gb = (size_t)(col0 + r) * K + kb * TBK + ch * 8;
        int so = r * TLD + ch * 8;
        cp16(tA + so, A + ga);
        cp16(tB + so, B + gb);
    }
    asm volatile("cp.async.commit_group;" ::: "memory");
}

__device__ __forceinline__ void g_core(
    __half* gsm, int t,
    const __half* A, const __half* B,
    int row0, int col0, int K)
{
    const int w  = t >> 5;
    const int wm = w & 3;
    const int wn = w >> 2;

    wmma::fragment<wmma::accumulator, 16, 16, 16, float> acc[2][4];
#pragma unroll
    for (int i = 0; i < 2; i++)
#pragma unroll
        for (int j = 0; j < 4; j++) wmma::fill_fragment(acc[i][j], 0.0f);

    const int nk = K / TBK;
    g_load_stage(gsm, 0, 0, t, A, B, row0, col0, K);
    g_load_stage(gsm, 1, 1, t, A, B, row0, col0, K);

    for (int kb = 0; kb < nk; kb++) {
        const int cur = kb % NSTAGE;
        if (kb + 2 < nk) {
            g_load_stage(gsm, (kb + 2) % NSTAGE, kb + 2, t, A, B, row0, col0, K);
            asm volatile("cp.async.wait_group 2;" ::: "memory");
        } else if (kb + 1 < nk) {
            asm volatile("cp.async.wait_group 1;" ::: "memory");
        } else {
            asm volatile("cp.async.wait_group 0;" ::: "memory");
        }
        __syncthreads();

        const __half* tA = gsm + (cur * 2 + 0) * TILE_ELEMS;
        const __half* tB = gsm + (cur * 2 + 1) * TILE_ELEMS;

#pragma unroll
        for (int kk = 0; kk < TBK; kk += 16) {
            wmma::fragment<wmma::matrix_b, 16, 16, 16, __half, wmma::col_major> bf[4];
#pragma unroll
            for (int j = 0; j < 4; j++)
                wmma::load_matrix_sync(bf[j], tB + (wn * 64 + j * 16) * TLD + kk, TLD);
#pragma unroll
            for (int i = 0; i < 2; i++) {
                wmma::fragment<wmma::matrix_a, 16, 16, 16, __half, wmma::row_major> af;
                wmma::load_matrix_sync(af, tA + (wm * 32 + i * 16) * TLD + kk, TLD);
#pragma unroll
                for (int j = 0; j < 4; j++)
                    wmma::mma_sync(acc[i][j], af, bf[j], acc[i][j]);
            }
        }
        __syncthreads();
    }

    float* smf = (float*)gsm;
#pragma unroll
    for (int i = 0; i < 2; i++)
#pragma unroll
        for (int j = 0; j < 4; j++)
            wmma::store_matrix_sync(&smf[(wm * 32 + i * 16) * SEPI + wn * 64 + j * 16],
                                    acc[i][j], SEPI, wmma::mem_row_major);
    __syncthreads();
}

// Fused Q/K/V projection. grid = (24, 32). 2 CTAs/SM.
__global__ __launch_bounds__(256, 2) void gemm_qkv(
    const __half* __restrict__ xp,
    const __half* __restrict__ wq, const __half* __restrict__ wk,
    const __half* __restrict__ wv,
    __half* __restrict__ qp, __half* __restrict__ kp,
    __half* __restrict__ vtp)
{
    extern __shared__ __half gsm[];
    const int t  = threadIdx.x;
    const int bx = blockIdx.x;
    const int row0 = blockIdx.y * TBM;

    const __half* B; int mode, N, cb;
    __half* C;
    if (bx < 16)      { B = wq; mode = 0; N = NE;  cb = bx;      C = qp; }
    else if (bx < 20) { B = wk; mode = 0; N = KVE; cb = bx - 16; C = kp; }
    else              { B = wv; mode = 1; N = KVE; cb = bx - 20; C = vtp; }
    const int col0 = cb * TBN;

    g_core(gsm, t, xp, B, row0, col0, NE);
    float* smf = (float*)gsm;

    if (mode == 0) {
#pragma unroll
        for (int i = 0; i < 32; i++) {
            int p = t + i * 256;
            int r = p >> 6, c2 = (p & 63) * 2;
            float x0 = smf[r * SEPI + c2], x1 = smf[r * SEPI + c2 + 1];
            size_t gidx = (size_t)(row0 + r) * N + col0 + c2;
            *(uint32_t*)&C[gidx] = pack_h(x0, x1);
        }
    } else {
        const int b  = row0 >> 11;
        const int t0 = row0 & 2047;
        const int hk = col0 >> 7;
#pragma unroll
        for (int i = 0; i < 32; i++) {
            int p = t + i * 256;
            int c = p >> 6, rp = (p & 63) * 2;
            float x0 = smf[rp * SEPI + c], x1 = smf[(rp + 1) * SEPI + c];
            size_t gidx = ((size_t)(b * NKV + hk) * HD + c) * TT + t0 + rp;
            *(uint32_t*)&C[gidx] = pack_h(x0, x1);
        }
    }
}

// Output projection: fp32 out. grid = (16, 32). 2 CTAs/SM.
__global__ __launch_bounds__(256, 2) void gemm_wo(
    const __half* __restrict__ yp,
    const __half* __restrict__ wo, float* __restrict__ out)
{
    extern __shared__ __half gsm[];
    const int t = threadIdx.x;
    const int row0 = blockIdx.y * TBM;
    const int col0 = blockIdx.x * TBN;

    g_core(gsm, t, yp, wo, row0, col0, NE);
    float* smf = (float*)gsm;
#pragma unroll
    for (int i = 0; i < 32; i++) {
        int p = t + i * 256;
        int r = p >> 6, c2 = (p & 63) * 2;
        float2 v = *(float2*)&smf[r * SEPI + c2];
        *(float2*)&out[(size_t)(row0 + r) * NE + col0 + c2] = v;
    }
}

// ---------------------------------------------------------------------------
// FA2 mma.sync causal GQA attention, fp16 1-term, Q staged in smem,
// KV tile 64, double-buffered cp.async. 2 CTAs/SM.
// ---------------------------------------------------------------------------
#define BQ 128
#define BKV 64
#define QSTR 136
#define KSTR 136
#define VSTR 72
#define QTILE (BQ * QSTR)             // 17408 halves
#define KTILE (BKV * KSTR)            // 8704 halves
#define VTILE (HD * VSTR)             // 9216 halves
#define ASTAGE (KTILE + VTILE)        // 17920 halves
#define SM_ATT_BYTES ((QTILE + 2 * ASTAGE) * 2)   // 106,496 B

__global__ __launch_bounds__(256, 2) void attn_mma(
    const __half* __restrict__ qp,
    const __half* __restrict__ kf, const __half* __restrict__ vtf,
    __half* __restrict__ yp) {
    extern __shared__ __half smA[];
    __half* Qs = smA;

    const int t    = threadIdx.x;
    const int w    = t >> 5;
    const int lane = t & 31;
    const int qb   = (gridDim.x - 1) - blockIdx.x;   // heavy CTAs first
    const int bh   = blockIdx.y;
    const int b    = bh >> 4;
    const int h    = bh & 15;
    const int hk   = h / GRP;
    const int q0   = qb * BQ;
    const int qrow = w * 16 + (lane >> 2);           // local q row (0..127)
    const int rg0  = q0 + qrow;
    const int rg1  = rg0 + 8;
    const int qpair = (lane & 3) * 2;

    // ---- stage Q tile into smem (async) ----
#pragma unroll
    for (int i = 0; i < 8; i++) {
        int p = t + i * 256;               // 0..2047
        int r = p >> 4, ch = p & 15;
        size_t g = ((size_t)(b * TT + q0 + r) * NH + h) * HD + ch * 8;
        cp16(Qs + r * QSTR + ch * 8, qp + g);
    }
    asm volatile("cp.async.commit_group;" ::: "memory");

    float O[16][4];
#pragma unroll
    for (int nt = 0; nt < 16; nt++)
#pragma unroll
        for (int e = 0; e < 4; e++) O[nt][e] = 0.0f;
    float m0 = -CUDART_INF_F, m1 = -CUDART_INF_F, l0 = 0.0f, l1 = 0.0f;

    const float SCL = 0.08838834764831845f * 1.4426950408889634f;
    const int kb_end = 2 * qb + 2;

    auto fill = [&](int st, int kb) {
        __half* Ksh = smA + QTILE + st * ASTAGE;
        __half* Vsh = Ksh + KTILE;
        const int k0 = kb * BKV;
#pragma unroll
        for (int i = 0; i < 4; i++) {
            int p = t + i * 256;
            int c = p >> 4, ch = p & 15;
            size_t g = ((size_t)(b * TT + k0 + c) * NKV + hk) * HD + ch * 8;
            cp16(Ksh + c * KSTR + ch * 8, kf + g);
        }
#pragma unroll
        for (int i = 0; i < 4; i++) {
            int p = t + i * 256;
            int d = p >> 3, ch = p & 7;
            size_t g = ((size_t)(b * NKV + hk) * HD + d) * TT + k0 + ch * 8;
            cp16(Vsh + d * VSTR + ch * 8, vtf + g);
        }
        asm volatile("cp.async.commit_group;" ::: "memory");
    };

    fill(0, 0);

    for (int kb = 0; kb < kb_end; kb++) {
        const int cur = kb & 1;
        const int k0 = kb * BKV;
        if (kb + 1 < kb_end) {
            fill(cur ^ 1, kb + 1);
            asm volatile("cp.async.wait_group 1;" ::: "memory");
        } else {
            asm volatile("cp.async.wait_group 0;" ::: "memory");
        }
        __syncthreads();

        const __half* Ksh = smA + QTILE + cur * ASTAGE;
        const __half* Vsh = Ksh + KTILE;

        // ---- S = Q K^T ----
        float S[8][4];
#pragma unroll
        for (int jt = 0; jt < 8; jt++)
#pragma unroll
            for (int e = 0; e < 4; e++) S[jt][e] = 0.0f;

#pragma unroll
        for (int kt = 0; kt < 8; kt++) {
            uint32_t Qf[4];
            int qb0 = qrow * QSTR + kt * 16 + qpair;
            Qf[0] = *(const uint32_t*)&Qs[qb0];
            Qf[1] = *(const uint32_t*)&Qs[qb0 + 8 * QSTR];
            Qf[2] = *(const uint32_t*)&Qs[qb0 + 8];
            Qf[3] = *(const uint32_t*)&Qs[qb0 + 8 * QSTR + 8];
#pragma unroll
            for (int jt = 0; jt < 8; jt++) {
                int base = (jt * 8 + (lane >> 2)) * KSTR + kt * 16 + qpair;
                uint32_t b0 = *(const uint32_t*)&Ksh[base];
                uint32_t b1 = *(const uint32_t*)&Ksh[base + 8];
                mma16816(S[jt], Qf, b0, b1);
            }
        }

        // ---- scale + causal mask ----
        const bool diag = (kb >= 2 * qb);
#pragma unroll
        for (int jt = 0; jt < 8; jt++) {
            int c0 = k0 + jt * 8 + qpair;
            S[jt][0] *= SCL; S[jt][1] *= SCL; S[jt][2] *= SCL; S[jt][3] *= SCL;
            if (diag) {
                if (c0 > rg0)     S[jt][0] = -CUDART_INF_F;
                if (c0 + 1 > rg0) S[jt][1] = -CUDART_INF_F;
                if (c0 > rg1)     S[jt][2] = -CUDART_INF_F;
                if (c0 + 1 > rg1) S[jt][3] = -CUDART_INF_F;
            }
        }

        // ---- online softmax (base-2) ----
        float mx0 = -CUDART_INF_F, mx1 = -CUDART_INF_F;
#pragma unroll
        for (int jt = 0; jt < 8; jt++) {
            mx0 = fmaxf(mx0, fmaxf(S[jt][0], S[jt][1]));
            mx1 = fmaxf(mx1, fmaxf(S[jt][2], S[jt][3]));
        }
#pragma unroll
        for (int off = 1; off <= 2; off <<= 1) {
            mx0 = fmaxf(mx0, __shfl_xor_sync(0xffffffffu, mx0, off));
            mx1 = fmaxf(mx1, __shfl_xor_sync(0xffffffffu, mx1, off));
        }
        float mn0 = fmaxf(m0, mx0), mn1 = fmaxf(m1, mx1);
        float al0 = fast_exp2(m0 - mn0), al1 = fast_exp2(m1 - mn1);
        float s0 = 0.0f, s1 = 0.0f;
#pragma unroll
        for (int jt = 0; jt < 8; jt++) {
            S[jt][0] = fast_exp2(S[jt][0] - mn0); s0 += S[jt][0];
            S[jt][1] = fast_exp2(S[jt][1] - mn0); s0 += S[jt][1];
            S[jt][2] = fast_exp2(S[jt][2] - mn1); s1 += S[jt][2];
            S[jt][3] = fast_exp2(S[jt][3] - mn1); s1 += S[jt][3];
        }
#pragma unroll
        for (int off = 1; off <= 2; off <<= 1) {
            s0 += __shfl_xor_sync(0xffffffffu, s0, off);
            s1 += __shfl_xor_sync(0xffffffffu, s1, off);
        }
        l0 = l0 * al0 + s0; l1 = l1 * al1 + s1;
        m0 = mn0; m1 = mn1;
#pragma unroll
        for (int nt = 0; nt < 16; nt++) {
            O[nt][0] *= al0; O[nt][1] *= al0;
            O[nt][2] *= al1; O[nt][3] *= al1;
        }

        // ---- O += P V ----
#pragma unroll
        for (int kt = 0; kt < 4; kt++) {
            uint32_t Ph[4];
            Ph[0] = pack_h(S[2 * kt][0],     S[2 * kt][1]);
            Ph[1] = pack_h(S[2 * kt][2],     S[2 * kt][3]);
            Ph[2] = pack_h(S[2 * kt + 1][0], S[2 * kt + 1][1]);
            Ph[3] = pack_h(S[2 * kt + 1][2], S[2 * kt + 1][3]);
#pragma unroll
            for (int nt = 0; nt < 16; nt++) {
                int base = (nt * 8 + (lane >> 2)) * VSTR + kt * 16 + qpair;
                uint32_t b0 = *(const uint32_t*)&Vsh[base];
                uint32_t b1 = *(const uint32_t*)&Vsh[base + 8];
                mma16816(O[nt], Ph, b0, b1);
            }
        }
        __syncthreads();
    }

    float il0 = 1.0f / l0, il1 = 1.0f / l1;
#pragma unroll
    for (int nt = 0; nt < 16; nt++) {
        int d = nt * 8 + qpair;
        size_t base0 = (size_t)(b * TT + rg0) * NE + h * HD + d;
        size_t base1 = (size_t)(b * TT + rg1) * NE + h * HD + d;
        *(uint32_t*)&yp[base0] = pack_h(O[nt][0] * il0, O[nt][1] * il0);
        *(uint32_t*)&yp[base1] = pack_h(O[nt][2] * il1, O[nt][3] * il1);
    }
}

// ---------------------------------------------------------------------------
extern "C" void kernel_launch(void* const* d_in, const int* in_sizes, int n_in,
                              void* d_out, int out_size) {
    const float* x  = (const float*)d_in[0];
    const float* wq = (const float*)d_in[1];
    const float* wk = (const float*)d_in[2];
    const float* wv = (const float*)d_in[3];
    const float* wo = (const float*)d_in[4];
    float* out = (float*)d_out;

    __half *xp, *wqp, *wkp, *wvp, *wop, *qp, *kp, *vtp, *yp;
    cudaGetSymbolAddress((void**)&xp,  g_x);
    cudaGetSymbolAddress((void**)&wqp, g_wq);  cudaGetSymbolAddress((void**)&wkp, g_wk);
    cudaGetSymbolAddress((void**)&wvp, g_wv);  cudaGetSymbolAddress((void**)&wop, g_wo);
    cudaGetSymbolAddress((void**)&qp,  g_q);
    cudaGetSymbolAddress((void**)&kp,  g_k);   cudaGetSymbolAddress((void**)&vtp, g_vt);
    cudaGetSymbolAddress((void**)&yp,  g_y);

    prep_all<<<(PREP_TOTAL + 255) / 256, 256>>>(x, wq, wk, wv, wo,
                                                xp, wqp, wkp, wvp, wop);

    cudaFuncSetAttribute(gemm_qkv, cudaFuncAttributeMaxDynamicSharedMemorySize, GEMM_SMEM);
    cudaFuncSetAttribute(gemm_wo,  cudaFuncAttributeMaxDynamicSharedMemorySize, GEMM_SMEM);

    dim3 blk(256);
    gemm_qkv<<<dim3(24, 32), blk, GEMM_SMEM>>>(xp, wqp, wkp, wvp, qp, kp, vtp);

    cudaFuncSetAttribute(attn_mma, cudaFuncAttributeMaxDynamicSharedMemorySize, SM_ATT_BYTES);
    attn_mma<<<dim3(TT / BQ, BB * NH), blk, SM_ATT_BYTES>>>(qp, kp, vtp, yp);

    gemm_wo<<<dim3(16, 32), blk, GEMM_SMEM>>>(yp, wop, out);
}

// round 15
// speedup vs baseline: 1.1205x; 1.1205x over previous
#include <cuda_runtime.h>
#include <cuda_fp16.h>
#include <math_constants.h>
#include <mma.h>
#include <cstdint>

using namespace nvcuda;

#define BB 2
#define TT 2048
#define NE 2048
#define NH 16
#define NKV 4
#define HD 128
#define GRP (NH / NKV)
#define MROWS (BB * TT)
#define KVE (NKV * HD)

// fp16 scratch
__device__ __half g_x[MROWS * NE];
__device__ __half g_wq[NE * NE];
__device__ __half g_wk[KVE * NE];
__device__ __half g_wv[KVE * NE];
__device__ __half g_wo[NE * NE];
__device__ __half g_q[MROWS * NE];     // (B,T,H,D) single fp16, pre-scaled
__device__ __half g_k[MROWS * KVE];    // (B,T,Hkv,D)
__device__ __half g_vt[MROWS * KVE];   // (B,Hkv,D,T)
__device__ __half g_y[MROWS * NE];

__device__ __forceinline__ uint32_t pack_h(float x, float y) {
    __half2 r = __floats2half2_rn(x, y);
    return *(uint32_t*)&r;
}
__device__ __forceinline__ float fast_exp2(float x) {
    float y; asm("ex2.approx.f32 %0, %1;" : "=f"(y) : "f"(x)); return y;
}
__device__ __forceinline__ void mma16816(float* c, const uint32_t* a, uint32_t b0, uint32_t b1) {
    asm volatile("mma.sync.aligned.m16n8k16.row.col.f32.f16.f16.f32 "
                 "{%0,%1,%2,%3}, {%4,%5,%6,%7}, {%8,%9}, {%0,%1,%2,%3};\n"
                 : "+f"(c[0]), "+f"(c[1]), "+f"(c[2]), "+f"(c[3])
                 : "r"(a[0]), "r"(a[1]), "r"(a[2]), "r"(a[3]), "r"(b0), "r"(b1));
}
__device__ __forceinline__ void cp16(__half* s, const __half* g) {
    uint32_t sa = (uint32_t)__cvta_generic_to_shared(s);
    asm volatile("cp.async.cg.shared.global [%0], [%1], 16;" :: "r"(sa), "l"(g));
}

// ---------------------------------------------------------------------------
// Fused prep: convert x, wq, wk, wv, wo -> single fp16
// ---------------------------------------------------------------------------
#define NX4  (MROWS * NE / 4)
#define NW4  (NE * NE / 4)
#define NWK4 (KVE * NE / 4)
#define PREP_TOTAL (NX4 + NW4 + 2 * NWK4 + NW4)

__global__ __launch_bounds__(256) void prep_all(
    const float* __restrict__ x,  const float* __restrict__ wq,
    const float* __restrict__ wk, const float* __restrict__ wv,
    const float* __restrict__ wo,
    __half* __restrict__ xp, __half* __restrict__ wqp,
    __half* __restrict__ wkp, __half* __restrict__ wvp,
    __half* __restrict__ wop)
{
    int i = blockIdx.x * blockDim.x + threadIdx.x;
    if (i >= PREP_TOTAL) return;
    const float* src; __half* dst; int j;
    if (i < NX4)                        { src = x;  dst = xp;  j = i; }
    else if (i < NX4 + NW4)             { src = wq; dst = wqp; j = i - NX4; }
    else if (i < NX4 + NW4 + NWK4)      { src = wk; dst = wkp; j = i - NX4 - NW4; }
    else if (i < NX4 + NW4 + 2*NWK4)    { src = wv; dst = wvp; j = i - NX4 - NW4 - NWK4; }
    else                                { src = wo; dst = wop; j = i - NX4 - NW4 - 2*NWK4; }
    float4 v = ((const float4*)src)[j];
    union { __half b[4]; uint2 u; } H;
    H.b[0] = __float2half_rn(v.x); H.b[1] = __float2half_rn(v.y);
    H.b[2] = __float2half_rn(v.z); H.b[3] = __float2half_rn(v.w);
    ((uint2*)dst)[j] = H.u;
}

// ---------------------------------------------------------------------------
// GEMM core: 2-stage cp.async, K-step 64, fp16 1-term.
// Block tile 128x128, 256 threads, 8 warps as 4x2, warp tile 32x64.
// 73,728 B smem/CTA -> 2 CTAs/SM.
// ---------------------------------------------------------------------------
#define TBM 128
#define TBN 128
#define TBK 64
#define TLD 72
#define TILE_ELEMS (TBM * TLD)     // 9216 halves
#define NSTAGE 2
#define SEPI 132
#define GEMM_SMEM (NSTAGE * 2 * TILE_ELEMS * 2)   // 73,728 B

__device__ __forceinline__ void g_load_stage(
    __half* gsm, int st, int kb, int t,
    const __half* A, const __half* B,
    int row0, int col0, int K)
{
    __half* tA = gsm + (st * 2 + 0) * TILE_ELEMS;
    __half* tB = gsm + (st * 2 + 1) * TILE_ELEMS;
#pragma unroll
    for (int i = 0; i < 4; i++) {
        int p = t + i * 256;
        int r = p >> 3, ch = p & 7;
        size_t ga = (size_t)(row0 + r) * K + kb * TBK + ch * 8;
        size_t gb = (size_t)(col0 + r) * K + kb * TBK + ch * 8;
        int so = r * TLD + ch * 8;
        cp16(tA + so, A + ga);
        cp16(tB + so, B + gb);
    }
    asm volatile("cp.async.commit_group;" ::: "memory");
}

__device__ __forceinline__ void g_core(
    __half* gsm, int t,
    const __half* A, const __half* B,
    int row0, int col0, int K)
{
    const int w  = t >> 5;
    const int wm = w & 3;
    const int wn = w >> 2;

    wmma::fragment<wmma::accumulator, 16, 16, 16, float> acc[2][4];
#pragma unroll
    for (int i = 0; i < 2; i++)
#pragma unroll
        for (int j = 0; j < 4; j++) wmma::fill_fragment(acc[i][j], 0.0f);

    const int nk = K / TBK;
    g_load_stage(gsm, 0, 0, t, A, B, row0, col0, K);

    for (int kb = 0; kb < nk; kb++) {
        const int cur = kb & 1;
        if (kb + 1 < nk) {
            g_load_stage(gsm, cur ^ 1, kb + 1, t, A, B, row0, col0, K);
            asm volatile("cp.async.wait_group 1;" ::: "memory");
        } else {
            asm volatile("cp.async.wait_group 0;" ::: "memory");
        }
        __syncthreads();

        const __half* tA = gsm + (cur * 2 + 0) * TILE_ELEMS;
        const __half* tB = gsm + (cur * 2 + 1) * TILE_ELEMS;

#pragma unroll
        for (int kk = 0; kk < TBK; kk += 16) {
            wmma::fragment<wmma::matrix_b, 16, 16, 16, __half, wmma::col_major> bf[4];
#pragma unroll
            for (int j = 0; j < 4; j++)
                wmma::load_matrix_sync(bf[j], tB + (wn * 64 + j * 16) * TLD + kk, TLD);
#pragma unroll
            for (int i = 0; i < 2; i++) {
                wmma::fragment<wmma::matrix_a, 16, 16, 16, __half, wmma::row_major> af;
                wmma::load_matrix_sync(af, tA + (wm * 32 + i * 16) * TLD + kk, TLD);
#pragma unroll
                for (int j = 0; j < 4; j++)
                    wmma::mma_sync(acc[i][j], af, bf[j], acc[i][j]);
            }
        }
        __syncthreads();
    }

    float* smf = (float*)gsm;
#pragma unroll
    for (int i = 0; i < 2; i++)
#pragma unroll
        for (int j = 0; j < 4; j++)
            wmma::store_matrix_sync(&smf[(wm * 32 + i * 16) * SEPI + wn * 64 + j * 16],
                                    acc[i][j], SEPI, wmma::mem_row_major);
    __syncthreads();
}

// Fused Q/K/V projection. grid = (24, 32). 2 CTAs/SM.
// bx 0..15: Q (pre-scaled), bx 16..19: K, bx 20..23: V^T.
__global__ __launch_bounds__(256, 2) void gemm_qkv(
    const __half* __restrict__ xp,
    const __half* __restrict__ wq, const __half* __restrict__ wk,
    const __half* __restrict__ wv,
    __half* __restrict__ qp, __half* __restrict__ kp,
    __half* __restrict__ vtp)
{
    extern __shared__ __half gsm[];
    const int t  = threadIdx.x;
    const int bx = blockIdx.x;
    const int row0 = blockIdx.y * TBM;
    const float QSCALE = 0.08838834764831845f * 1.4426950408889634f;

    const __half* B; int mode, N, cb;
    __half* C;
    if (bx < 16)      { B = wq; mode = 2; N = NE;  cb = bx;      C = qp; }
    else if (bx < 20) { B = wk; mode = 0; N = KVE; cb = bx - 16; C = kp; }
    else              { B = wv; mode = 1; N = KVE; cb = bx - 20; C = vtp; }
    const int col0 = cb * TBN;

    g_core(gsm, t, xp, B, row0, col0, NE);
    float* smf = (float*)gsm;

    if (mode == 2) {
        // Q: scale by 1/sqrt(D)*log2(e) before fp16 rounding
#pragma unroll
        for (int i = 0; i < 32; i++) {
            int p = t + i * 256;
            int r = p >> 6, c2 = (p & 63) * 2;
            float x0 = smf[r * SEPI + c2] * QSCALE, x1 = smf[r * SEPI + c2 + 1] * QSCALE;
            size_t gidx = (size_t)(row0 + r) * N + col0 + c2;
            *(uint32_t*)&C[gidx] = pack_h(x0, x1);
        }
    } else if (mode == 0) {
#pragma unroll
        for (int i = 0; i < 32; i++) {
            int p = t + i * 256;
            int r = p >> 6, c2 = (p & 63) * 2;
            float x0 = smf[r * SEPI + c2], x1 = smf[r * SEPI + c2 + 1];
            size_t gidx = (size_t)(row0 + r) * N + col0 + c2;
            *(uint32_t*)&C[gidx] = pack_h(x0, x1);
        }
    } else {
        const int b  = row0 >> 11;
        const int t0 = row0 & 2047;
        const int hk = col0 >> 7;
#pragma unroll
        for (int i = 0; i < 32; i++) {
            int p = t + i * 256;
            int c = p >> 6, rp = (p & 63) * 2;
            float x0 = smf[rp * SEPI + c], x1 = smf[(rp + 1) * SEPI + c];
            size_t gidx = ((size_t)(b * NKV + hk) * HD + c) * TT + t0 + rp;
            *(uint32_t*)&C[gidx] = pack_h(x0, x1);
        }
    }
}

// Output projection: fp32 out. grid = (16, 32). 2 CTAs/SM.
__global__ __launch_bounds__(256, 2) void gemm_wo(
    const __half* __restrict__ yp,
    const __half* __restrict__ wo, float* __restrict__ out)
{
    extern __shared__ __half gsm[];
    const int t = threadIdx.x;
    const int row0 = blockIdx.y * TBM;
    const int col0 = blockIdx.x * TBN;

    g_core(gsm, t, yp, wo, row0, col0, NE);
    float* smf = (float*)gsm;
#pragma unroll
    for (int i = 0; i < 32; i++) {
        int p = t + i * 256;
        int r = p >> 6, c2 = (p & 63) * 2;
        float2 v = *(float2*)&smf[r * SEPI + c2];
        *(float2*)&out[(size_t)(row0 + r) * NE + col0 + c2] = v;
    }
}

// ---------------------------------------------------------------------------
// FA2 mma.sync causal GQA attention, fp16 1-term (Q pre-scaled, P single),
// KV tile 128, double-buffered cp.async. Writes single fp16 y. (R13 design)
// ---------------------------------------------------------------------------
#define BQ 128
#define BKV 128
#define KSTR 136
#define VSTR 136
#define KTILE (BKV * KSTR)
#define VTILE (HD * VSTR)
#define ASTAGE (KTILE + VTILE)
#define SM_ATT_BYTES (2 * ASTAGE * 2) // 139,264 B

__global__ __launch_bounds__(256, 1) void attn_mma(
    const __half* __restrict__ qp,
    const __half* __restrict__ kf, const __half* __restrict__ vtf,
    __half* __restrict__ yp) {
    extern __shared__ __half smA[];

    const int t    = threadIdx.x;
    const int w    = t >> 5;
    const int lane = t & 31;
    const int qb   = (gridDim.x - 1) - blockIdx.x;   // heavy CTAs first
    const int bh   = blockIdx.y;
    const int b    = bh >> 4;
    const int h    = bh & 15;
    const int hk   = h / GRP;
    const int q0   = qb * BQ;
    const int rg0  = q0 + w * 16 + (lane >> 2);
    const int rg1  = rg0 + 8;
    const int qpair = (lane & 3) * 2;

    uint32_t Qf[8][4];
#pragma unroll
    for (int kt = 0; kt < 8; kt++) {
#pragma unroll
        for (int half = 0; half < 2; half++) {
#pragma unroll
            for (int ri = 0; ri < 2; ri++) {
                int row = ri ? rg1 : rg0;
                size_t gi = ((size_t)(b * TT + row) * NH + h) * HD + kt * 16 + half * 8 + qpair;
                Qf[kt][half * 2 + ri] = *(const uint32_t*)&qp[gi];
            }
        }
    }

    float O[16][4];
#pragma unroll
    for (int nt = 0; nt < 16; nt++)
#pragma unroll
        for (int e = 0; e < 4; e++) O[nt][e] = 0.0f;
    float m0 = -CUDART_INF_F, m1 = -CUDART_INF_F, l0 = 0.0f, l1 = 0.0f;

    const int kb_end = qb + 1;

    auto fill = [&](int st, int kb) {
        __half* Ksh = smA + st * ASTAGE;
        __half* Vsh = Ksh + KTILE;
        const int k0 = kb * BKV;
#pragma unroll
        for (int i = 0; i < 8; i++) {
            int p = t + i * 256;
            int c = p >> 4, ch = p & 15;
            size_t g = ((size_t)(b * TT + k0 + c) * NKV + hk) * HD + ch * 8;
            cp16(Ksh + c * KSTR + ch * 8, kf + g);
        }
#pragma unroll
        for (int i = 0; i < 8; i++) {
            int p = t + i * 256;
            int d = p >> 4, ch = p & 15;
            size_t g = ((size_t)(b * NKV + hk) * HD + d) * TT + k0 + ch * 8;
            cp16(Vsh + d * VSTR + ch * 8, vtf + g);
        }
        asm volatile("cp.async.commit_group;" ::: "memory");
    };

    fill(0, 0);

    for (int kb = 0; kb < kb_end; kb++) {
        const int cur = kb & 1;
        const int k0 = kb * BKV;
        if (kb + 1 < kb_end) {
            fill(cur ^ 1, kb + 1);
            asm volatile("cp.async.wait_group 1;" ::: "memory");
        } else {
            asm volatile("cp.async.wait_group 0;" ::: "memory");
        }
        __syncthreads();

        const __half* Ksh = smA + cur * ASTAGE;
        const __half* Vsh = Ksh + KTILE;

        float S[16][4];
#pragma unroll
        for (int jt = 0; jt < 16; jt++)
#pragma unroll
            for (int e = 0; e < 4; e++) S[jt][e] = 0.0f;

#pragma unroll
        for (int kt = 0; kt < 8; kt++) {
#pragma unroll
            for (int jt = 0; jt < 16; jt++) {
                int base = (jt * 8 + (lane >> 2)) * KSTR + kt * 16 + qpair;
                uint32_t b0 = *(const uint32_t*)&Ksh[base];
                uint32_t b1 = *(const uint32_t*)&Ksh[base + 8];
                mma16816(S[jt], Qf[kt], b0, b1);
            }
        }

        // ---- causal mask (scale pre-folded into Q) ----
        const bool diag = (kb == qb);
        if (diag) {
#pragma unroll
            for (int jt = 0; jt < 16; jt++) {
                int c0 = k0 + jt * 8 + qpair;
                if (c0 > rg0)     S[jt][0] = -CUDART_INF_F;
                if (c0 + 1 > rg0) S[jt][1] = -CUDART_INF_F;
                if (c0 > rg1)     S[jt][2] = -CUDART_INF_F;
                if (c0 + 1 > rg1) S[jt][3] = -CUDART_INF_F;
            }
        }

        float mx0 = -CUDART_INF_F, mx1 = -CUDART_INF_F;
#pragma unroll
        for (int jt = 0; jt < 16; jt++) {
            mx0 = fmaxf(mx0, fmaxf(S[jt][0], S[jt][1]));
            mx1 = fmaxf(mx1, fmaxf(S[jt][2], S[jt][3]));
        }
#pragma unroll
        for (int off = 1; off <= 2; off <<= 1) {
            mx0 = fmaxf(mx0, __shfl_xor_sync(0xffffffffu, mx0, off));
            mx1 = fmaxf(mx1, __shfl_xor_sync(0xffffffffu, mx1, off));
        }
        float mn0 = fmaxf(m0, mx0), mn1 = fmaxf(m1, mx1);
        float al0 = fast_exp2(m0 - mn0), al1 = fast_exp2(m1 - mn1);
        float s0 = 0.0f, s1 = 0.0f;
#pragma unroll
        for (int jt = 0; jt < 16; jt++) {
            S[jt][0] = fast_exp2(S[jt][0] - mn0); s0 += S[jt][0];
            S[jt][1] = fast_exp2(S[jt][1] - mn0); s0 += S[jt][1];
            S[jt][2] = fast_exp2(S[jt][2] - mn1); s1 += S[jt][2];
            S[jt][3] = fast_exp2(S[jt][3] - mn1); s1 += S[jt][3];
        }
#pragma unroll
        for (int off = 1; off <= 2; off <<= 1) {
            s0 += __shfl_xor_sync(0xffffffffu, s0, off);
            s1 += __shfl_xor_sync(0xffffffffu, s1, off);
        }
        l0 = l0 * al0 + s0; l1 = l1 * al1 + s1;
        m0 = mn0; m1 = mn1;
#pragma unroll
        for (int nt = 0; nt < 16; nt++) {
            O[nt][0] *= al0; O[nt][1] *= al0;
            O[nt][2] *= al1; O[nt][3] *= al1;
        }

#pragma unroll
        for (int kt = 0; kt < 8; kt++) {
            uint32_t Ph[4];
            Ph[0] = pack_h(S[2 * kt][0],     S[2 * kt][1]);
            Ph[1] = pack_h(S[2 * kt][2],     S[2 * kt][3]);
            Ph[2] = pack_h(S[2 * kt + 1][0], S[2 * kt + 1][1]);
            Ph[3] = pack_h(S[2 * kt + 1][2], S[2 * kt + 1][3]);
#pragma unroll
            for (int nt = 0; nt < 16; nt++) {
                int base = (nt * 8 + (lane >> 2)) * VSTR + kt * 16 + qpair;
                uint32_t b0 = *(const uint32_t*)&Vsh[base];
                uint32_t b1 = *(const uint32_t*)&Vsh[base + 8];
                mma16816(O[nt], Ph, b0, b1);
            }
        }
        __syncthreads();
    }

    float il0 = 1.0f / l0, il1 = 1.0f / l1;
#pragma unroll
    for (int nt = 0; nt < 16; nt++) {
        int d = nt * 8 + qpair;
        size_t base0 = (size_t)(b * TT + rg0) * NE + h * HD + d;
        size_t base1 = (size_t)(b * TT + rg1) * NE + h * HD + d;
        *(uint32_t*)&yp[base0] = pack_h(O[nt][0] * il0, O[nt][1] * il0);
        *(uint32_t*)&yp[base1] = pack_h(O[nt][2] * il1, O[nt][3] * il1);
    }
}

// ---------------------------------------------------------------------------
extern "C" void kernel_launch(void* const* d_in, const int* in_sizes, int n_in,
                              void* d_out, int out_size) {
    const float* x  = (const float*)d_in[0];
    const float* wq = (const float*)d_in[1];
    const float* wk = (const float*)d_in[2];
    const float* wv = (const float*)d_in[3];
    const float* wo = (const float*)d_in[4];
    float* out = (float*)d_out;

    __half *xp, *wqp, *wkp, *wvp, *wop, *qp, *kp, *vtp, *yp;
    cudaGetSymbolAddress((void**)&xp,  g_x);
    cudaGetSymbolAddress((void**)&wqp, g_wq);  cudaGetSymbolAddress((void**)&wkp, g_wk);
    cudaGetSymbolAddress((void**)&wvp, g_wv);  cudaGetSymbolAddress((void**)&wop, g_wo);
    cudaGetSymbolAddress((void**)&qp,  g_q);
    cudaGetSymbolAddress((void**)&kp,  g_k);   cudaGetSymbolAddress((void**)&vtp, g_vt);
    cudaGetSymbolAddress((void**)&yp,  g_y);

    prep_all<<<(PREP_TOTAL + 255) / 256, 256>>>(x, wq, wk, wv, wo,
                                                xp, wqp, wkp, wvp, wop);

    cudaFuncSetAttribute(gemm_qkv, cudaFuncAttributeMaxDynamicSharedMemorySize, GEMM_SMEM);
    cudaFuncSetAttribute(gemm_wo,  cudaFuncAttributeMaxDynamicSharedMemorySize, GEMM_SMEM);

    dim3 blk(256);
    gemm_qkv<<<dim3(24, 32), blk, GEMM_SMEM>>>(xp, wqp, wkp, wvp, qp, kp, vtp);

    cudaFuncSetAttribute(attn_mma, cudaFuncAttributeMaxDynamicSharedMemorySize, SM_ATT_BYTES);
    attn_mma<<<dim3(TT / BQ, BB * NH), blk, SM_ATT_BYTES>>>(qp, kp, vtp, yp);

    gemm_wo<<<dim3(16, 32), blk, GEMM_SMEM>>>(yp, wop, out);
}

// round 16
// speedup vs baseline: 1.1264x; 1.0053x over previous
#include <cuda_runtime.h>
#include <cuda_fp16.h>
#include <math_constants.h>
#include <mma.h>
#include <cstdint>

using namespace nvcuda;

#define BB 2
#define TT 2048
#define NE 2048
#define NH 16
#define NKV 4
#define HD 128
#define GRP (NH / NKV)
#define MROWS (BB * TT)
#define KVE (NKV * HD)

// fp16 scratch
__device__ __half g_x[MROWS * NE];
__device__ __half g_wq[NE * NE];
__device__ __half g_wk[KVE * NE];
__device__ __half g_wv[KVE * NE];
__device__ __half g_wo[NE * NE];
__device__ __half g_q[MROWS * NE];     // (B,T,H,D) single fp16, pre-scaled
__device__ __half g_k[MROWS * KVE];    // (B,T,Hkv,D)
__device__ __half g_vt[MROWS * KVE];   // (B,Hkv,D,T)
__device__ __half g_y[MROWS * NE];

__device__ __forceinline__ uint32_t pack_h(float x, float y) {
    __half2 r = __floats2half2_rn(x, y);
    return *(uint32_t*)&r;
}
__device__ __forceinline__ float fast_exp2(float x) {
    float y; asm("ex2.approx.f32 %0, %1;" : "=f"(y) : "f"(x)); return y;
}
__device__ __forceinline__ void mma16816(float* c, const uint32_t* a, uint32_t b0, uint32_t b1) {
    asm volatile("mma.sync.aligned.m16n8k16.row.col.f32.f16.f16.f32 "
                 "{%0,%1,%2,%3}, {%4,%5,%6,%7}, {%8,%9}, {%0,%1,%2,%3};\n"
                 : "+f"(c[0]), "+f"(c[1]), "+f"(c[2]), "+f"(c[3])
                 : "r"(a[0]), "r"(a[1]), "r"(a[2]), "r"(a[3]), "r"(b0), "r"(b1));
}
__device__ __forceinline__ void cp16(__half* s, const __half* g) {
    uint32_t sa = (uint32_t)__cvta_generic_to_shared(s);
    asm volatile("cp.async.cg.shared.global [%0], [%1], 16;" :: "r"(sa), "l"(g));
}

// ---------------------------------------------------------------------------
// Fused prep: convert x, wq, wk, wv, wo -> single fp16
// ---------------------------------------------------------------------------
#define NX4  (MROWS * NE / 4)
#define NW4  (NE * NE / 4)
#define NWK4 (KVE * NE / 4)
#define PREP_TOTAL (NX4 + NW4 + 2 * NWK4 + NW4)

__global__ __launch_bounds__(256) void prep_all(
    const float* __restrict__ x,  const float* __restrict__ wq,
    const float* __restrict__ wk, const float* __restrict__ wv,
    const float* __restrict__ wo,
    __half* __restrict__ xp, __half* __restrict__ wqp,
    __half* __restrict__ wkp, __half* __restrict__ wvp,
    __half* __restrict__ wop)
{
    int i = blockIdx.x * blockDim.x + threadIdx.x;
    if (i >= PREP_TOTAL) return;
    const float* src; __half* dst; int j;
    if (i < NX4)                        { src = x;  dst = xp;  j = i; }
    else if (i < NX4 + NW4)             { src = wq; dst = wqp; j = i - NX4; }
    else if (i < NX4 + NW4 + NWK4)      { src = wk; dst = wkp; j = i - NX4 - NW4; }
    else if (i < NX4 + NW4 + 2*NWK4)    { src = wv; dst = wvp; j = i - NX4 - NW4 - NWK4; }
    else                                { src = wo; dst = wop; j = i - NX4 - NW4 - 2*NWK4; }
    float4 v = ((const float4*)src)[j];
    union { __half b[4]; uint2 u; } H;
    H.b[0] = __float2half_rn(v.x); H.b[1] = __float2half_rn(v.y);
    H.b[2] = __float2half_rn(v.z); H.b[3] = __float2half_rn(v.w);
    ((uint2*)dst)[j] = H.u;
}

// ---------------------------------------------------------------------------
// GEMM core: 2-stage cp.async, K-step 64, fp16 1-term.
// Block tile 128x128, 256 threads, 8 warps as 4x2, warp tile 32x64.
// 73,728 B smem/CTA -> 2 CTAs/SM.
// If gout != nullptr, accumulators are stored directly to global fp32
// (row-major, ld = gldm); otherwise staged into smem (SEPI stride).
// ---------------------------------------------------------------------------
#define TBM 128
#define TBN 128
#define TBK 64
#define TLD 72
#define TILE_ELEMS (TBM * TLD)     // 9216 halves
#define NSTAGE 2
#define SEPI 132
#define GEMM_SMEM (NSTAGE * 2 * TILE_ELEMS * 2)   // 73,728 B

__device__ __forceinline__ void g_load_stage(
    __half* gsm, int st, int kb, int t,
    const __half* A, const __half* B,
    int row0, int col0, int K)
{
    __half* tA = gsm + (st * 2 + 0) * TILE_ELEMS;
    __half* tB = gsm + (st * 2 + 1) * TILE_ELEMS;
#pragma unroll
    for (int i = 0; i < 4; i++) {
        int p = t + i * 256;
        int r = p >> 3, ch = p & 7;
        size_t ga = (size_t)(row0 + r) * K + kb * TBK + ch * 8;
        size_t gb = (size_t)(col0 + r) * K + kb * TBK + ch * 8;
        int so = r * TLD + ch * 8;
        cp16(tA + so, A + ga);
        cp16(tB + so, B + gb);
    }
    asm volatile("cp.async.commit_group;" ::: "memory");
}

__device__ __forceinline__ void g_core(
    __half* gsm, int t,
    const __half* A, const __half* B,
    int row0, int col0, int K,
    float* gout, int gldm)
{
    const int w  = t >> 5;
    const int wm = w & 3;
    const int wn = w >> 2;

    wmma::fragment<wmma::accumulator, 16, 16, 16, float> acc[2][4];
#pragma unroll
    for (int i = 0; i < 2; i++)
#pragma unroll
        for (int j = 0; j < 4; j++) wmma::fill_fragment(acc[i][j], 0.0f);

    const int nk = K / TBK;
    g_load_stage(gsm, 0, 0, t, A, B, row0, col0, K);

    for (int kb = 0; kb < nk; kb++) {
        const int cur = kb & 1;
        if (kb + 1 < nk) {
            g_load_stage(gsm, cur ^ 1, kb + 1, t, A, B, row0, col0, K);
            asm volatile("cp.async.wait_group 1;" ::: "memory");
        } else {
            asm volatile("cp.async.wait_group 0;" ::: "memory");
        }
        __syncthreads();

        const __half* tA = gsm + (cur * 2 + 0) * TILE_ELEMS;
        const __half* tB = gsm + (cur * 2 + 1) * TILE_ELEMS;

#pragma unroll
        for (int kk = 0; kk < TBK; kk += 16) {
            wmma::fragment<wmma::matrix_b, 16, 16, 16, __half, wmma::col_major> bf[4];
#pragma unroll
            for (int j = 0; j < 4; j++)
                wmma::load_matrix_sync(bf[j], tB + (wn * 64 + j * 16) * TLD + kk, TLD);
#pragma unroll
            for (int i = 0; i < 2; i++) {
                wmma::fragment<wmma::matrix_a, 16, 16, 16, __half, wmma::row_major> af;
                wmma::load_matrix_sync(af, tA + (wm * 32 + i * 16) * TLD + kk, TLD);
#pragma unroll
                for (int j = 0; j < 4; j++)
                    wmma::mma_sync(acc[i][j], af, bf[j], acc[i][j]);
            }
        }
        __syncthreads();
    }

    if (gout) {
        // direct global store (fp32 row-major)
#pragma unroll
        for (int i = 0; i < 2; i++)
#pragma unroll
            for (int j = 0; j < 4; j++)
                wmma::store_matrix_sync(
                    &gout[(size_t)(wm * 32 + i * 16) * gldm + wn * 64 + j * 16],
                    acc[i][j], gldm, wmma::mem_row_major);
    } else {
        float* smf = (float*)gsm;
#pragma unroll
        for (int i = 0; i < 2; i++)
#pragma unroll
            for (int j = 0; j < 4; j++)
                wmma::store_matrix_sync(&smf[(wm * 32 + i * 16) * SEPI + wn * 64 + j * 16],
                                        acc[i][j], SEPI, wmma::mem_row_major);
        __syncthreads();
    }
}

// Fused Q/K/V projection. grid = (24, 32). 2 CTAs/SM.
// bx 0..15: Q (pre-scaled), bx 16..19: K, bx 20..23: V^T.
__global__ __launch_bounds__(256, 2) void gemm_qkv(
    const __half* __restrict__ xp,
    const __half* __restrict__ wq, const __half* __restrict__ wk,
    const __half* __restrict__ wv,
    __half* __restrict__ qp, __half* __restrict__ kp,
    __half* __restrict__ vtp)
{
    extern __shared__ __half gsm[];
    const int t  = threadIdx.x;
    const int bx = blockIdx.x;
    const int row0 = blockIdx.y * TBM;
    const float QSCALE = 0.08838834764831845f * 1.4426950408889634f;

    const __half* B; int mode, N, cb;
    __half* C;
    if (bx < 16)      { B = wq; mode = 2; N = NE;  cb = bx;      C = qp; }
    else if (bx < 20) { B = wk; mode = 0; N = KVE; cb = bx - 16; C = kp; }
    else              { B = wv; mode = 1; N = KVE; cb = bx - 20; C = vtp; }
    const int col0 = cb * TBN;

    g_core(gsm, t, xp, B, row0, col0, NE, nullptr, 0);
    float* smf = (float*)gsm;

    if (mode == 2) {
#pragma unroll
        for (int i = 0; i < 32; i++) {
            int p = t + i * 256;
            int r = p >> 6, c2 = (p & 63) * 2;
            float x0 = smf[r * SEPI + c2] * QSCALE, x1 = smf[r * SEPI + c2 + 1] * QSCALE;
            size_t gidx = (size_t)(row0 + r) * N + col0 + c2;
            *(uint32_t*)&C[gidx] = pack_h(x0, x1);
        }
    } else if (mode == 0) {
#pragma unroll
        for (int i = 0; i < 32; i++) {
            int p = t + i * 256;
            int r = p >> 6, c2 = (p & 63) * 2;
            float x0 = smf[r * SEPI + c2], x1 = smf[r * SEPI + c2 + 1];
            size_t gidx = (size_t)(row0 + r) * N + col0 + c2;
            *(uint32_t*)&C[gidx] = pack_h(x0, x1);
        }
    } else {
        const int b  = row0 >> 11;
        const int t0 = row0 & 2047;
        const int hk = col0 >> 7;
#pragma unroll
        for (int i = 0; i < 32; i++) {
            int p = t + i * 256;
            int c = p >> 6, rp = (p & 63) * 2;
            float x0 = smf[rp * SEPI + c], x1 = smf[(rp + 1) * SEPI + c];
            size_t gidx = ((size_t)(b * NKV + hk) * HD + c) * TT + t0 + rp;
            *(uint32_t*)&C[gidx] = pack_h(x0, x1);
        }
    }
}

// Output projection: fp32 out, direct fragment store. grid = (16, 32). 2 CTAs/SM.
__global__ __launch_bounds__(256, 2) void gemm_wo(
    const __half* __restrict__ yp,
    const __half* __restrict__ wo, float* __restrict__ out)
{
    extern __shared__ __half gsm[];
    const int t = threadIdx.x;
    const int row0 = blockIdx.y * TBM;
    const int col0 = blockIdx.x * TBN;

    g_core(gsm, t, yp, wo, row0, col0, NE,
           out + (size_t)row0 * NE + col0, NE);
}

// ---------------------------------------------------------------------------
// FA2 mma.sync causal GQA attention, fp16 1-term (Q pre-scaled, P single),
// KV tile 128, double-buffered cp.async, merged K/V fill. (R15 design)
// ---------------------------------------------------------------------------
#define BQ 128
#define BKV 128
#define KSTR 136
#define VSTR 136
#define KTILE (BKV * KSTR)
#define VTILE (HD * VSTR)
#define ASTAGE (KTILE + VTILE)
#define SM_ATT_BYTES (2 * ASTAGE * 2) // 139,264 B

__global__ __launch_bounds__(256, 1) void attn_mma(
    const __half* __restrict__ qp,
    const __half* __restrict__ kf, const __half* __restrict__ vtf,
    __half* __restrict__ yp) {
    extern __shared__ __half smA[];

    const int t    = threadIdx.x;
    const int w    = t >> 5;
    const int lane = t & 31;
    const int qb   = (gridDim.x - 1) - blockIdx.x;   // heavy CTAs first
    const int bh   = blockIdx.y;
    const int b    = bh >> 4;
    const int h    = bh & 15;
    const int hk   = h / GRP;
    const int q0   = qb * BQ;
    const int rg0  = q0 + w * 16 + (lane >> 2);
    const int rg1  = rg0 + 8;
    const int qpair = (lane & 3) * 2;

    uint32_t Qf[8][4];
#pragma unroll
    for (int kt = 0; kt < 8; kt++) {
#pragma unroll
        for (int half = 0; half < 2; half++) {
#pragma unroll
            for (int ri = 0; ri < 2; ri++) {
                int row = ri ? rg1 : rg0;
                size_t gi = ((size_t)(b * TT + row) * NH + h) * HD + kt * 16 + half * 8 + qpair;
                Qf[kt][half * 2 + ri] = *(const uint32_t*)&qp[gi];
            }
        }
    }

    float O[16][4];
#pragma unroll
    for (int nt = 0; nt < 16; nt++)
#pragma unroll
        for (int e = 0; e < 4; e++) O[nt][e] = 0.0f;
    float m0 = -CUDART_INF_F, m1 = -CUDART_INF_F, l0 = 0.0f, l1 = 0.0f;

    const int kb_end = qb + 1;

    auto fill = [&](int st, int kb) {
        __half* Ksh = smA + st * ASTAGE;
        __half* Vsh = Ksh + KTILE;
        const int k0 = kb * BKV;
        // merged K (rows x d) + V^T (d x rows) fill: 16 iterations
#pragma unroll
        for (int i = 0; i < 16; i++) {
            int p = t + i * 256;               // 0..4095
            if (p < 2048) {
                int c = p >> 4, ch = p & 15;
                size_t g = ((size_t)(b * TT + k0 + c) * NKV + hk) * HD + ch * 8;
                cp16(Ksh + c * KSTR + ch * 8, kf + g);
            } else {
                int q2 = p - 2048;
                int d = q2 >> 4, ch = q2 & 15;
                size_t g = ((size_t)(b * NKV + hk) * HD + d) * TT + k0 + ch * 8;
                cp16(Vsh + d * VSTR + ch * 8, vtf + g);
            }
        }
        asm volatile("cp.async.commit_group;" ::: "memory");
    };

    fill(0, 0);

    for (int kb = 0; kb < kb_end; kb++) {
        const int cur = kb & 1;
        const int k0 = kb * BKV;
        if (kb + 1 < kb_end) {
            fill(cur ^ 1, kb + 1);
            asm volatile("cp.async.wait_group 1;" ::: "memory");
        } else {
            asm volatile("cp.async.wait_group 0;" ::: "memory");
        }
        __syncthreads();

        const __half* Ksh = smA + cur * ASTAGE;
        const __half* Vsh = Ksh + KTILE;

        float S[16][4];
#pragma unroll
        for (int jt = 0; jt < 16; jt++)
#pragma unroll
            for (int e = 0; e < 4; e++) S[jt][e] = 0.0f;

#pragma unroll
        for (int kt = 0; kt < 8; kt++) {
#pragma unroll
            for (int jt = 0; jt < 16; jt++) {
                int base = (jt * 8 + (lane >> 2)) * KSTR + kt * 16 + qpair;
                uint32_t b0 = *(const uint32_t*)&Ksh[base];
                uint32_t b1 = *(const uint32_t*)&Ksh[base + 8];
                mma16816(S[jt], Qf[kt], b0, b1);
            }
        }

        const bool diag = (kb == qb);
        if (diag) {
#pragma unroll
            for (int jt = 0; jt < 16; jt++) {
                int c0 = k0 + jt * 8 + qpair;
                if (c0 > rg0)     S[jt][0] = -CUDART_INF_F;
                if (c0 + 1 > rg0) S[jt][1] = -CUDART_INF_F;
                if (c0 > rg1)     S[jt][2] = -CUDART_INF_F;
                if (c0 + 1 > rg1) S[jt][3] = -CUDART_INF_F;
            }
        }

        float mx0 = -CUDART_INF_F, mx1 = -CUDART_INF_F;
#pragma unroll
        for (int jt = 0; jt < 16; jt++) {
            mx0 = fmaxf(mx0, fmaxf(S[jt][0], S[jt][1]));
            mx1 = fmaxf(mx1, fmaxf(S[jt][2], S[jt][3]));
        }
#pragma unroll
        for (int off = 1; off <= 2; off <<= 1) {
            mx0 = fmaxf(mx0, __shfl_xor_sync(0xffffffffu, mx0, off));
            mx1 = fmaxf(mx1, __shfl_xor_sync(0xffffffffu, mx1, off));
        }
        float mn0 = fmaxf(m0, mx0), mn1 = fmaxf(m1, mx1);
        float al0 = fast_exp2(m0 - mn0), al1 = fast_exp2(m1 - mn1);
        float s0 = 0.0f, s1 = 0.0f;
#pragma unroll
        for (int jt = 0; jt < 16; jt++) {
            S[jt][0] = fast_exp2(S[jt][0] - mn0); s0 += S[jt][0];
            S[jt][1] = fast_exp2(S[jt][1] - mn0); s0 += S[jt][1];
            S[jt][2] = fast_exp2(S[jt][2] - mn1); s1 += S[jt][2];
            S[jt][3] = fast_exp2(S[jt][3] - mn1); s1 += S[jt][3];
        }
#pragma unroll
        for (int off = 1; off <= 2; off <<= 1) {
            s0 += __shfl_xor_sync(0xffffffffu, s0, off);
            s1 += __shfl_xor_sync(0xffffffffu, s1, off);
        }
        l0 = l0 * al0 + s0; l1 = l1 * al1 + s1;
        m0 = mn0; m1 = mn1;
#pragma unroll
        for (int nt = 0; nt < 16; nt++) {
            O[nt][0] *= al0; O[nt][1] *= al0;
            O[nt][2] *= al1; O[nt][3] *= al1;
        }

#pragma unroll
        for (int kt = 0; kt < 8; kt++) {
            uint32_t Ph[4];
            Ph[0] = pack_h(S[2 * kt][0],     S[2 * kt][1]);
            Ph[1] = pack_h(S[2 * kt][2],     S[2 * kt][3]);
            Ph[2] = pack_h(S[2 * kt + 1][0], S[2 * kt + 1][1]);
            Ph[3] = pack_h(S[2 * kt + 1][2], S[2 * kt + 1][3]);
#pragma unroll
            for (int nt = 0; nt < 16; nt++) {
                int base = (nt * 8 + (lane >> 2)) * VSTR + kt * 16 + qpair;
                uint32_t b0 = *(const uint32_t*)&Vsh[base];
                uint32_t b1 = *(const uint32_t*)&Vsh[base + 8];
                mma16816(O[nt], Ph, b0, b1);
            }
        }
        __syncthreads();
    }

    float il0 = 1.0f / l0, il1 = 1.0f / l1;
#pragma unroll
    for (int nt = 0; nt < 16; nt++) {
        int d = nt * 8 + qpair;
        size_t base0 = (size_t)(b * TT + rg0) * NE + h * HD + d;
        size_t base1 = (size_t)(b * TT + rg1) * NE + h * HD + d;
        *(uint32_t*)&yp[base0] = pack_h(O[nt][0] * il0, O[nt][1] * il0);
        *(uint32_t*)&yp[base1] = pack_h(O[nt][2] * il1, O[nt][3] * il1);
    }
}

// ---------------------------------------------------------------------------
extern "C" void kernel_launch(void* const* d_in, const int* in_sizes, int n_in,
                              void* d_out, int out_size) {
    const float* x  = (const float*)d_in[0];
    const float* wq = (const float*)d_in[1];
    const float* wk = (const float*)d_in[2];
    const float* wv = (const float*)d_in[3];
    const float* wo = (const float*)d_in[4];
    float* out = (float*)d_out;

    __half *xp, *wqp, *wkp, *wvp, *wop, *qp, *kp, *vtp, *yp;
    cudaGetSymbolAddress((void**)&xp,  g_x);
    cudaGetSymbolAddress((void**)&wqp, g_wq);  cudaGetSymbolAddress((void**)&wkp, g_wk);
    cudaGetSymbolAddress((void**)&wvp, g_wv);  cudaGetSymbolAddress((void**)&wop, g_wo);
    cudaGetSymbolAddress((void**)&qp,  g_q);
    cudaGetSymbolAddress((void**)&kp,  g_k);   cudaGetSymbolAddress((void**)&vtp, g_vt);
    cudaGetSymbolAddress((void**)&yp,  g_y);

    prep_all<<<(PREP_TOTAL + 255) / 256, 256>>>(x, wq, wk, wv, wo,
                                                xp, wqp, wkp, wvp, wop);

    cudaFuncSetAttribute(gemm_qkv, cudaFuncAttributeMaxDynamicSharedMemorySize, GEMM_SMEM);
    cudaFuncSetAttribute(gemm_wo,  cudaFuncAttributeMaxDynamicSharedMemorySize, GEMM_SMEM);

    dim3 blk(256);
    gemm_qkv<<<dim3(24, 32), blk, GEMM_SMEM>>>(xp, wqp, wkp, wvp, qp, kp, vtp);

    cudaFuncSetAttribute(attn_mma, cudaFuncAttributeMaxDynamicSharedMemorySize, SM_ATT_BYTES);
    attn_mma<<<dim3(TT / BQ, BB * NH), blk, SM_ATT_BYTES>>>(qp, kp, vtp, yp);

    gemm_wo<<<dim3(16, 32), blk, GEMM_SMEM>>>(yp, wop, out);
}